// round 15
// baseline (speedup 1.0000x reference)
#include <cuda_runtime.h>
#include <cuda_fp16.h>
#include <cstdint>

// Problem constants: B=4, C=T=16, n=1024, KS=3
// out = softmax_ch( cos_att * relu(x_gc_t + x) )

// ---------------- scratch (device globals) ----------------------------------
__device__ float g_XM[1024 * 2048];                        // GEMM result
__device__ float g_cos[64 * 1024 * 16];                    // [bc][i][t]  (dense)
__device__ __align__(16) __half g_Afh[1024 * 1024];        // x_tmp fp16 hi, K-major
__device__ __align__(16) __half g_Afl[1024 * 1024];        // fp16 residual
__device__ __align__(16) __half g_Bf [2048 * 1024];        // Lk2^T fp16, K-major
__device__ __align__(16) __half g_Xnh[64 * 1024 * 16];     // (x/||x||)[bc][i][t] hi
__device__ __align__(16) __half g_Xnl[64 * 1024 * 16];     // residual
__device__ __align__(16) __half g_XTfh[64 * 16 * 1024];    // x[bc][t][i] fp16 hi
__device__ __align__(16) __half g_XTfl[64 * 16 * 1024];    // fp16 residual
__device__ __align__(16) __half g_bpermh[131072 * 8];      // beta fp16 frags

// ---------------- helpers ----------------------------------------------------
__device__ __forceinline__ uint32_t smem_u32(const void* p) {
    uint32_t a;
    asm("{ .reg .u64 t; cvta.to.shared.u64 t, %1; cvt.u32.u64 %0, t; }"
        : "=r"(a) : "l"(p));
    return a;
}
__device__ __forceinline__ void cp_async16(uint32_t dst, const void* src) {
    asm volatile("cp.async.cg.shared.global [%0], [%1], 16;" :: "r"(dst), "l"(src));
}
__device__ __forceinline__ void cp_commit() {
    asm volatile("cp.async.commit_group;" ::: "memory");
}
template <int N> __device__ __forceinline__ void cp_wait() {
    asm volatile("cp.async.wait_group %0;" :: "n"(N) : "memory");
}
__device__ __forceinline__ void mma16816f16(float* d, const uint32_t* a,
                                            const uint32_t* b) {
    asm volatile(
        "mma.sync.aligned.m16n8k16.row.col.f32.f16.f16.f32 "
        "{%0,%1,%2,%3}, {%4,%5,%6,%7}, {%8,%9}, {%0,%1,%2,%3};\n"
        : "+f"(d[0]), "+f"(d[1]), "+f"(d[2]), "+f"(d[3])
        : "r"(a[0]), "r"(a[1]), "r"(a[2]), "r"(a[3]), "r"(b[0]), "r"(b[1]));
}
__device__ __forceinline__ void ldsm_x4(uint32_t* r, uint32_t addr) {
    asm volatile("ldmatrix.sync.aligned.m8n8.x4.shared.b16 {%0,%1,%2,%3}, [%4];"
                 : "=r"(r[0]), "=r"(r[1]), "=r"(r[2]), "=r"(r[3]) : "r"(addr));
}
__device__ __forceinline__ uint32_t pack_f16x2(float hi, float lo) {
    uint32_t r;
    asm("cvt.rn.f16x2.f32 %0, %1, %2;" : "=r"(r) : "f"(hi), "f"(lo));
    return r;
}
// sigmoid(z) = 0.5 * tanh(z/2) + 0.5  (1 MUFU)
__device__ __forceinline__ float sig_tanh(float z) {
    float t;
    asm("tanh.approx.f32 %0, %1;" : "=f"(t) : "f"(0.5f * z));
    return fmaf(0.5f, t, 0.5f);
}
__device__ __forceinline__ float2 h2f(uint32_t u) {
    __half2 h = *(__half2*)&u;
    return __half22float2(h);   // .x = low half, .y = high half
}

// =============================================================================
// Prepass bodies
// =============================================================================
// P1: one block per (bc, quarter) — 256 blocks.
__device__ __forceinline__ void p1_body(uint8_t* spre, const float* __restrict__ x,
                                        int g, int c)
{
    float (*s)[258] = (float(*)[258])spre;
    const int tid = threadIdx.x;
#pragma unroll
    for (int it = 0; it < 16; it++) {
        int idx = tid + it * 256;                 // i_local*16 + t
        float v = x[g * 16384 + c * 4096 + idx];
        s[idx & 15][idx >> 4] = v;
    }
    __syncthreads();
    {   // (a) A matrices (fp16 hi/lo for k1): row = g*16 + t, cols i
        const int rl = tid >> 4;
        const int kk0 = (tid & 15) * 16;
        alignas(16) __half hb[16], lb[16];
#pragma unroll
        for (int q = 0; q < 16; q++) {
            float v = s[rl][kk0 + q];
            __half h = __float2half(v);
            hb[q] = h;
            lb[q] = __float2half(v - __half2float(h));
        }
        size_t off = (size_t)(g * 16 + rl) * 1024 + c * 256 + kk0;
        *(uint4*)(g_Afh + off)     = *(uint4*)(hb);
        *(uint4*)(g_Afh + off + 8) = *(uint4*)(hb + 8);
        *(uint4*)(g_Afl + off)     = *(uint4*)(lb);
        *(uint4*)(g_Afl + off + 8) = *(uint4*)(lb + 8);
    }
    {   // (b) normalized X rows (fp16 hi + residual)
        const int i = c * 256 + tid;
        float s2 = 0.f;
#pragma unroll
        for (int t = 0; t < 16; t++) {
            float v = s[t][tid];
            s2 = fmaf(v, v, s2);
        }
        const float inv = rsqrtf(s2);
        alignas(16) __half hb[16], lb[16];
#pragma unroll
        for (int t = 0; t < 16; t++) {
            float v = s[t][tid] * inv;
            __half h = __float2half(v);
            hb[t] = h;
            lb[t] = __float2half(v - __half2float(h));
        }
        size_t off = (size_t)(g * 1024 + i) * 16;
        *(uint4*)(g_Xnh + off)     = *(uint4*)(hb);
        *(uint4*)(g_Xnh + off + 8) = *(uint4*)(hb + 8);
        *(uint4*)(g_Xnl + off)     = *(uint4*)(lb);
        *(uint4*)(g_Xnl + off + 8) = *(uint4*)(lb + 8);
    }
    {   // (c) XT rows (fp16 hi + residual, unnormalized)
        const int t = tid >> 4;
        const int ib = (tid & 15) * 16;
        alignas(16) __half hb[16], lb[16];
#pragma unroll
        for (int q = 0; q < 16; q++) {
            float v = s[t][ib + q];
            __half h = __float2half(v);
            hb[q] = h;
            lb[q] = __float2half(v - __half2float(h));
        }
        size_t off = (size_t)(g * 16 + t) * 1024 + c * 256 + ib;
        *(uint4*)(g_XTfh + off)     = *(uint4*)(hb);
        *(uint4*)(g_XTfh + off + 8) = *(uint4*)(hb + 8);
        *(uint4*)(g_XTfl + off)     = *(uint4*)(lb);
        *(uint4*)(g_XTfl + off + 8) = *(uint4*)(lb + 8);
    }
}

// P2: 64x64 tiles -> single fp16 B
__device__ __forceinline__ void p2_body(uint8_t* spre, const float* __restrict__ Lk,
                                        int jt, int kt)
{
    float (*s)[65] = (float(*)[65])spre;   // [64 j][65]
    const int tid = threadIdx.x;
#pragma unroll
    for (int q = 0; q < 16; q++) {
        int idx = tid + q * 256;
        int row = idx >> 6;       // k-local 0..63
        int col = idx & 63;       // j-local
        s[col][row] = Lk[(kt * 64 + row) * 3072 + 1024 + jt * 64 + col];
    }
    __syncthreads();
#pragma unroll
    for (int q = 0; q < 4; q++) {
        int u = tid + q * 256;
        int jy = u >> 4;              // 0..63
        int kg = (u & 15) * 4;        // 0..60
        alignas(8) __half hb[4];
#pragma unroll
        for (int w = 0; w < 4; w++)
            hb[w] = __float2half(s[jy][kg + w]);
        size_t off = (size_t)(jt * 64 + jy) * 1024 + kt * 64 + kg;
        *(uint64_t*)(g_Bf + off) = *(uint64_t*)hb;
    }
}

// P3: beta -> fragment-ordered fp16 (8 halves = 16B per lane-entry)
__device__ __forceinline__ void p3_body(const float* __restrict__ beta, int blk)
{
    const int idx = blk * 256 + threadIdx.x;    // 0..131071
    const int lane = idx & 31;
    const int js = (idx >> 5) & 63;
    const int ib = idx >> 11;
    const int g = lane >> 2, tg = lane & 3;
    const int r0 = ib * 16 + g, r1 = r0 + 8;
    const int c0 = js * 16 + 2 * tg, c1 = c0 + 8;
    const float* b0 = beta + (size_t)r0 * 1024;
    const float* b1 = beta + (size_t)r1 * 1024;
    float2 a0 = *(const float2*)(b0 + c0);
    float2 a1 = *(const float2*)(b0 + c1);
    float2 a2 = *(const float2*)(b1 + c0);
    float2 a3 = *(const float2*)(b1 + c1);
    alignas(16) __half hb[8];
    hb[0] = __float2half(a0.x); hb[1] = __float2half(a0.y);
    hb[2] = __float2half(a1.x); hb[3] = __float2half(a1.y);
    hb[4] = __float2half(a2.x); hb[5] = __float2half(a2.y);
    hb[6] = __float2half(a3.x); hb[7] = __float2half(a3.y);
    *(uint4*)(g_bpermh + (size_t)idx * 8) = *(uint4*)hb;
}

__global__ __launch_bounds__(256) void k_pre(const float* __restrict__ x,
                                             const float* __restrict__ Lk,
                                             const float* __restrict__ beta)
{
    __shared__ __align__(16) uint8_t spre[16640];
    const int bid = blockIdx.x;
    if (bid < 256) p1_body(spre, x, bid >> 2, bid & 3);
    else if (bid < 768) p2_body(spre, Lk, (bid - 256) & 31, (bid - 256) >> 5);
    else p3_body(beta, bid - 768);
}

// =============================================================================
// Heavy fused kernel: even blocks = k1 GEMM tile, odd blocks = k3t attention.
// =============================================================================
// K1 fp16 2-pass: (Ahi + Alo) x B_single.
// stage s at sm + s*8192: Afh[0,2048) Afl[2048,4096) Bf[4096,8192)
__device__ __forceinline__ void k1_body(uint8_t* sm, int bid)
{
    const int tid = threadIdx.x;
    const int wid = tid >> 5, lane = tid & 31;
    const int g = lane >> 2, tg = lane & 3;
    const int wm = (wid & 3) * 16;
    const int wn = (wid >> 2) * 64;
    const int row0 = (bid >> 4) * 64;
    const int col0 = (bid & 15) * 128;

    const __half* Asrc_h = g_Afh + (size_t)row0 * 1024;
    const __half* Asrc_l = g_Afl + (size_t)row0 * 1024;
    const __half* Bsrc   = g_Bf  + (size_t)col0 * 1024;

    float acc[8][4];
#pragma unroll
    for (int nt = 0; nt < 8; nt++)
#pragma unroll
        for (int q = 0; q < 4; q++) acc[nt][q] = 0.f;

    auto load_stage = [&](int s, int kt) {
#pragma unroll
        for (int q = 0; q < 2; q++) {
            int idx = tid + q * 256;          // 0..511
            const __half* src;
            uint32_t arr_off;
            int rc;
            if (idx < 256) {                  // A: 64 rows x 2 chunks, hi|lo
                rc = idx & 127;
                src = (idx < 128) ? Asrc_h : Asrc_l;
                arr_off = (idx < 128) ? 0 : 2048;
            } else {                          // B: 128 rows x 2 chunks
                rc = idx - 256;
                src = Bsrc;
                arr_off = 4096;
            }
            int r = rc >> 1, c = rc & 1;
            uint32_t dst = smem_u32(sm) + s * 8192 + arr_off + r * 32 +
                           ((c * 16) ^ (((r >> 2) & 1) << 4));
            cp_async16(dst, src + (size_t)r * 1024 + kt * 16 + c * 8);
        }
        cp_commit();
    };

    uint32_t offA, offB[4];
    {
        int arow = ((lane >> 3) & 1) * 8 + (lane & 7);
        int cA = lane >> 4;
        int brow = ((lane >> 4) << 3) + (lane & 7);
        int cB = (lane >> 3) & 1;
        int rA = wm + arow;
        offA = rA * 32 + ((cA ^ ((rA >> 2) & 1)) << 4);
#pragma unroll
        for (int p = 0; p < 4; p++) {
            int r = wn + p * 16 + brow;
            offB[p] = r * 32 + ((cB ^ ((r >> 2) & 1)) << 4);
        }
    }

    load_stage(0, 0);
    load_stage(1, 1);

    int sread = 0;
    for (int kt = 0; kt < 64; kt++) {
        if (kt < 63) cp_wait<1>(); else cp_wait<0>();
        __syncthreads();
        if (kt + 2 < 64) {
            int sw = sread + 2; if (sw >= 3) sw -= 3;
            load_stage(sw, kt + 2);
        }

        const uint32_t base = smem_u32(sm) + sread * 8192;

        uint32_t ah[4], al[4], bf[4][4];
        ldsm_x4(ah, base + offA);
        ldsm_x4(al, base + 2048 + offA);
#pragma unroll
        for (int p = 0; p < 4; p++)
            ldsm_x4(bf[p], base + 4096 + offB[p]);

#pragma unroll
        for (int nt = 0; nt < 8; nt++)
            mma16816f16(acc[nt], ah, &bf[nt >> 1][(nt & 1) * 2]);
#pragma unroll
        for (int nt = 0; nt < 8; nt++)
            mma16816f16(acc[nt], al, &bf[nt >> 1][(nt & 1) * 2]);

        sread = (sread + 1 == 3) ? 0 : sread + 1;
    }
#pragma unroll
    for (int nt = 0; nt < 8; nt++) {
        int r = row0 + wm + g;
        int c = col0 + wn + nt * 8 + tg * 2;
        *(float2*)&g_XM[(size_t)r * 2048 + c] =
            make_float2(acc[nt][0], acc[nt][1]);
        *(float2*)&g_XM[(size_t)(r + 8) * 2048 + c] =
            make_float2(acc[nt][2], acc[nt][3]);
    }
}

// K3T: S = 2-pass fp16 on PRE-NORMALIZED rows (Xn hi/lo x Xn-hi) => S = cos.
// PV = 3-pass fp16 (Phi x XTh + Phi x XTl + Plo x XTh).
// stage st at sm + st*12288: Xn[0,4096) XTh[4096,8192) XTl[8192,12288)
__device__ __forceinline__ void k3t_body(uint8_t* sm, int bid)
{
    const int tid  = threadIdx.x;
    const int lane = tid & 31, wid = tid >> 5;
    const int g = lane >> 2, tg = lane & 3;
    const int bc = bid >> 2;
    const int i0 = (bid & 3) * 256;

    const int rw = i0 + wid * 32;
    const int ib0 = rw >> 4;

    uint32_t aih[2][4], ail[2][4];
#pragma unroll
    for (int p = 0; p < 2; p++) {
        const int r = rw + 16 * p + g;
        const uint32_t* Xh = (const uint32_t*)(g_Xnh + ((size_t)bc * 1024 + r) * 16);
        const uint32_t* Xl = (const uint32_t*)(g_Xnl + ((size_t)bc * 1024 + r) * 16);
        aih[p][0] = Xh[tg];      aih[p][1] = Xh[64 + tg];
        aih[p][2] = Xh[tg + 4];  aih[p][3] = Xh[64 + tg + 4];
        ail[p][0] = Xl[tg];      ail[p][1] = Xl[64 + tg];
        ail[p][2] = Xl[tg + 4];  ail[p][3] = Xl[64 + tg + 4];
    }

    float o[2][2][4];
#pragma unroll
    for (int p = 0; p < 2; p++)
#pragma unroll
        for (int u = 0; u < 2; u++)
#pragma unroll
            for (int q = 0; q < 4; q++) o[p][u][q] = 0.f;

    const int jr = ((lane >> 4) << 3) + (lane & 7);
    const int cS = (lane >> 3) & 1;
    const uint32_t offS = (uint32_t)(jr * 32 + ((cS ^ ((jr >> 2) & 1)) << 4));
    const int tl = jr;
    const int cbit = (lane >> 3) & 1;

    auto stage = [&](int st, int jt) {
        const size_t xb = ((size_t)bc * 1024 + jt * 128) * 32;   // bytes (fp16 row 32B)
        const size_t tb = ((size_t)bc * 16384 + jt * 128) * 2;   // bytes
        const char* srcs[3] = {(const char*)g_Xnh + xb,
                               (const char*)g_XTfh + tb, (const char*)g_XTfl + tb};
#pragma unroll
        for (int a = 0; a < 3; a++) {
            int q = tid;
            uint32_t dst;
            const char* src;
            if (a == 0) {
                int j = q >> 1, c = q & 1;
                dst = (uint32_t)(j * 32 + ((c ^ ((j >> 2) & 1)) << 4));
                src = srcs[0] + (size_t)j * 32 + c * 16;
            } else {
                int t = q >> 4, c = q & 15;
                dst = (uint32_t)(t * 256 + ((c ^ t) << 4));
                src = srcs[a] + (size_t)t * 2048 + c * 16;
            }
            cp_async16(smem_u32(sm) + st * 12288 + a * 4096 + dst, src);
        }
        cp_commit();
    };

    stage(0, 0);

    for (int jt = 0; jt < 8; jt++) {
        cp_wait<0>();
        __syncthreads();
        if (jt < 7) stage((jt + 1) & 1, jt + 1);

        const uint32_t sbase = smem_u32(sm) + (jt & 1) * 12288;

#pragma unroll 2
        for (int s2 = 0; s2 < 8; s2++) {
            const int js = s2 * 16;
            const int jstep = jt * 8 + s2;

            // hoisted beta fragment loads (1 LDG.128 per pair)
            const uint4* bp0 = (const uint4*)g_bpermh +
                               (((size_t)ib0 * 64 + jstep) * 32 + lane);
            uint4 raw0 = bp0[0];
            uint4 raw1 = bp0[64 * 32];     // ib0+1

            uint32_t bh4[4];
            ldsm_x4(bh4, sbase + js * 32 + offS);
            const uint32_t cj = 2 * s2 + cbit;
            const uint32_t offP = (uint32_t)(tl * 256 + ((cj ^ tl) << 4));
            uint32_t th4[4], tl4[4];
            ldsm_x4(th4, sbase + 4096 + offP);
            ldsm_x4(tl4, sbase + 8192 + offP);

#pragma unroll
            for (int p = 0; p < 2; p++) {
                uint4 raw = (p == 0) ? raw0 : raw1;
                float2 w0 = h2f(raw.x);   // row g:   j0, j0+1
                float2 w1 = h2f(raw.y);   // row g:   j8, j8+1
                float2 w2 = h2f(raw.z);   // row 8+g: j0, j0+1
                float2 w3 = h2f(raw.w);   // row 8+g: j8, j8+1

                float s0[4] = {0.f, 0.f, 0.f, 0.f};
                float s1[4] = {0.f, 0.f, 0.f, 0.f};
                mma16816f16(s0, aih[p], &bh4[0]);
                mma16816f16(s0, ail[p], &bh4[0]);
                mma16816f16(s1, aih[p], &bh4[2]);
                mma16816f16(s1, ail[p], &bh4[2]);

                float p00 = sig_tanh(w0.x * s0[0]);
                float p01 = sig_tanh(w0.y * s0[1]);
                float p02 = sig_tanh(w2.x * s0[2]);
                float p03 = sig_tanh(w2.y * s0[3]);
                float p10 = sig_tanh(w1.x * s1[0]);
                float p11 = sig_tanh(w1.y * s1[1]);
                float p12 = sig_tanh(w3.x * s1[2]);
                float p13 = sig_tanh(w3.y * s1[3]);

                // P split: hi fp16 + residual fp16
                uint32_t pah[4], pal[4];
                pah[0] = pack_f16x2(p01, p00);
                pah[1] = pack_f16x2(p03, p02);
                pah[2] = pack_f16x2(p11, p10);
                pah[3] = pack_f16x2(p13, p12);
                {
                    float2 b0 = h2f(pah[0]), b1 = h2f(pah[1]);
                    float2 b2 = h2f(pah[2]), b3 = h2f(pah[3]);
                    pal[0] = pack_f16x2(p01 - b0.y, p00 - b0.x);
                    pal[1] = pack_f16x2(p03 - b1.y, p02 - b1.x);
                    pal[2] = pack_f16x2(p11 - b2.y, p10 - b2.x);
                    pal[3] = pack_f16x2(p13 - b3.y, p12 - b3.x);
                }

                mma16816f16(o[p][0], pah, &th4[0]);
                mma16816f16(o[p][0], pah, &tl4[0]);
                mma16816f16(o[p][0], pal, &th4[0]);
                mma16816f16(o[p][1], pah, &th4[2]);
                mma16816f16(o[p][1], pah, &tl4[2]);
                mma16816f16(o[p][1], pal, &th4[2]);
            }
        }
    }

    // epilogue: dense float2 stores into g_cos[bc][i][t]
#pragma unroll
    for (int p = 0; p < 2; p++) {
        const int r = rw + 16 * p + g;
        float* base0 = g_cos + ((size_t)bc * 1024 + r) * 16;      // row r
        float* base1 = base0 + 8 * 16;                            // row r+8
        *(float2*)(base0 + 2 * tg)     = make_float2(o[p][0][0], o[p][0][1]);
        *(float2*)(base1 + 2 * tg)     = make_float2(o[p][0][2], o[p][0][3]);
        *(float2*)(base0 + 8 + 2 * tg) = make_float2(o[p][1][0], o[p][1][1]);
        *(float2*)(base1 + 8 + 2 * tg) = make_float2(o[p][1][2], o[p][1][3]);
    }
}

__global__ __launch_bounds__(256, 2) void k_heavy()
{
    __shared__ __align__(16) uint8_t sm[24576];
    if ((blockIdx.x & 1) == 0) k1_body(sm, blockIdx.x >> 1);
    else                       k3t_body(sm, blockIdx.x >> 1);
}

// =============================================================================
// K_POST: fused theta-fold + relu/mul + channel softmax.
// =============================================================================
__global__ __launch_bounds__(256) void k_post(const float* __restrict__ x,
                                              const float* __restrict__ theta,
                                              const float* __restrict__ bias,
                                              float* __restrict__ out)
{
    __shared__ float th[768];
    __shared__ float bs[16];
    __shared__ float sx[16][16][17];     // [c][il][t]
    __shared__ float scos[16][272];      // [ch][t*17 + il]

    const int tid = threadIdx.x;
    const int tau = tid >> 4, il = tid & 15;
    const int b  = blockIdx.x >> 6;
    const int i0 = (blockIdx.x & 63) * 16;
    const int i  = i0 + il;

    for (int q = tid; q < 768; q += 256) th[q] = theta[q];
    if (tid < 16) bs[tid] = bias[tid];

    // stage cos: per ch, 256 consecutive floats (16 i x 16 t), coalesced
    {
        const int il2 = tid >> 4, tau2 = tid & 15;
#pragma unroll
        for (int ch = 0; ch < 16; ch++)
            scos[ch][tau2 * 17 + il2] =
                g_cos[((size_t)(b * 16 + ch) << 14) + i0 * 16 + tid];
    }

    const float* xr = x + (((b << 4) + tau) << 14) + (i << 4);
    float xrow[16];
#pragma unroll
    for (int q = 0; q < 4; q++)
        *(float4*)(xrow + 4 * q) = *(const float4*)(xr + 4 * q);
#pragma unroll
    for (int q = 0; q < 16; q++) sx[tau][il][q] = xrow[q];
    __syncthreads();

    float acc[16];
#pragma unroll
    for (int c = 0; c < 16; c++) acc[c] = bs[c];

    const int rbase = (b << 8) + (tau << 4);
#pragma unroll 4
    for (int tp = 0; tp < 16; ++tp) {
        const float* xm = g_XM + (size_t)(rbase + tp) * 2048 + i;
        float a0 = xrow[tp];
        float a1 = xm[0];
        float a2 = xm[1024];
        const float* t0 = th + tp * 48;
#pragma unroll
        for (int c = 0; c < 16; c++)
            acc[c] += a0 * t0[c] + a1 * t0[16 + c] + a2 * t0[32 + c];
    }

    float gg[16];
#pragma unroll
    for (int c = 0; c < 16; c++) {
        float xv = sx[c][il][tau];          // x[b][c][i][tau]
        float r = acc[c] + xv;
        r = r > 0.f ? r : 0.f;
        gg[c] = scos[c][tau * 17 + il] * r; // cos[b,c][i][tau]
    }
    float m = gg[0];
#pragma unroll
    for (int c = 1; c < 16; c++) m = fmaxf(m, gg[c]);
    float s = 0.f;
#pragma unroll
    for (int c = 0; c < 16; c++) {
        float e = __expf(gg[c] - m);
        gg[c] = e;
        s += e;
    }
    float rs = __fdividef(1.f, s);

#pragma unroll
    for (int c = 0; c < 16; c++) sx[c][il][tau] = gg[c] * rs;
    __syncthreads();

    float* dst = out + (((b << 4) + tau) << 14) + (i << 4);
#pragma unroll
    for (int t = 0; t < 16; t++) dst[t] = sx[tau][il][t];
}

// =============================================================================
extern "C" void kernel_launch(void* const* d_in, const int* in_sizes, int n_in,
                              void* d_out, int out_size)
{
    const float* x     = (const float*)d_in[0];
    const float* beta  = (const float*)d_in[1];
    const float* theta = (const float*)d_in[2];
    const float* bias  = (const float*)d_in[3];
    const float* Lk    = (const float*)d_in[4];
    float* out = (float*)d_out;

    k_pre<<<1280, 256>>>(x, Lk, beta);
    k_heavy<<<512, 256>>>();
    k_post<<<256, 256>>>(x, theta, bias, out);
}

// round 16
// speedup vs baseline: 1.4116x; 1.4116x over previous
#include <cuda_runtime.h>
#include <cuda_fp16.h>
#include <cstdint>

// Problem constants: B=4, C=T=16, n=1024, KS=3
// out = softmax_ch( cos_att * relu(x_gc_t + x) )

// ---------------- scratch (device globals) ----------------------------------
__device__ float g_XM[1024 * 2048];                        // GEMM result
__device__ float g_cos[64 * 1024 * 16];                    // [bc][i][t]  (dense)
__device__ __align__(16) __half g_Afh[1024 * 1024];        // x_tmp fp16 hi, K-major
__device__ __align__(16) __half g_Afl[1024 * 1024];        // fp16 residual
__device__ __align__(16) __half g_Bf [2048 * 1024];        // Lk2^T fp16, K-major
__device__ __align__(16) __half g_Xfh[64 * 1024 * 16];     // x[bc][i][t] fp16 hi
__device__ __align__(16) __half g_Xfl[64 * 1024 * 16];     // fp16 residual
__device__ __align__(16) __half g_XTfh[64 * 16 * 1024];    // x[bc][t][i] fp16 hi
__device__ __align__(16) __half g_XTfl[64 * 16 * 1024];    // fp16 residual
__device__ float g_inorm[64 * 1024];                       // 1/||x_i||
__device__ __align__(16) __half g_bpermh[131072 * 8];      // beta fp16 frags

// ---------------- helpers ----------------------------------------------------
__device__ __forceinline__ uint32_t smem_u32(const void* p) {
    uint32_t a;
    asm("{ .reg .u64 t; cvta.to.shared.u64 t, %1; cvt.u32.u64 %0, t; }"
        : "=r"(a) : "l"(p));
    return a;
}
__device__ __forceinline__ void cp_async16(uint32_t dst, const void* src) {
    asm volatile("cp.async.cg.shared.global [%0], [%1], 16;" :: "r"(dst), "l"(src));
}
__device__ __forceinline__ void cp_commit() {
    asm volatile("cp.async.commit_group;" ::: "memory");
}
template <int N> __device__ __forceinline__ void cp_wait() {
    asm volatile("cp.async.wait_group %0;" :: "n"(N) : "memory");
}
__device__ __forceinline__ void mma16816f16(float* d, const uint32_t* a,
                                            const uint32_t* b) {
    asm volatile(
        "mma.sync.aligned.m16n8k16.row.col.f32.f16.f16.f32 "
        "{%0,%1,%2,%3}, {%4,%5,%6,%7}, {%8,%9}, {%0,%1,%2,%3};\n"
        : "+f"(d[0]), "+f"(d[1]), "+f"(d[2]), "+f"(d[3])
        : "r"(a[0]), "r"(a[1]), "r"(a[2]), "r"(a[3]), "r"(b[0]), "r"(b[1]));
}
__device__ __forceinline__ void ldsm_x4(uint32_t* r, uint32_t addr) {
    asm volatile("ldmatrix.sync.aligned.m8n8.x4.shared.b16 {%0,%1,%2,%3}, [%4];"
                 : "=r"(r[0]), "=r"(r[1]), "=r"(r[2]), "=r"(r[3]) : "r"(addr));
}
__device__ __forceinline__ uint32_t pack_f16x2(float hi, float lo) {
    uint32_t r;
    asm("cvt.rn.f16x2.f32 %0, %1, %2;" : "=r"(r) : "f"(hi), "f"(lo));
    return r;
}
// sigmoid(z) = 0.5 * tanh(z/2) + 0.5  (1 MUFU)
__device__ __forceinline__ float sig_tanh(float z) {
    float t;
    asm("tanh.approx.f32 %0, %1;" : "=f"(t) : "f"(0.5f * z));
    return fmaf(0.5f, t, 0.5f);
}
__device__ __forceinline__ float2 h2f(uint32_t u) {
    __half2 h = *(__half2*)&u;
    return __half22float2(h);   // .x = low half, .y = high half
}

// =============================================================================
// Prepass bodies
// =============================================================================
// P1: one block per (bc, quarter) — 256 blocks.
__device__ __forceinline__ void p1_body(uint8_t* spre, const float* __restrict__ x,
                                        int g, int c)
{
    float (*s)[258] = (float(*)[258])spre;
    const int tid = threadIdx.x;
#pragma unroll
    for (int it = 0; it < 16; it++) {
        int idx = tid + it * 256;                 // i_local*16 + t
        float v = x[g * 16384 + c * 4096 + idx];
        s[idx & 15][idx >> 4] = v;
    }
    __syncthreads();
    {   // (a) A matrices (fp16 hi/lo for k1): row = g*16 + t, cols i
        const int rl = tid >> 4;
        const int kk0 = (tid & 15) * 16;
        alignas(16) __half hb[16], lb[16];
#pragma unroll
        for (int q = 0; q < 16; q++) {
            float v = s[rl][kk0 + q];
            __half h = __float2half(v);
            hb[q] = h;
            lb[q] = __float2half(v - __half2float(h));
        }
        size_t off = (size_t)(g * 16 + rl) * 1024 + c * 256 + kk0;
        *(uint4*)(g_Afh + off)     = *(uint4*)(hb);
        *(uint4*)(g_Afh + off + 8) = *(uint4*)(hb + 8);
        *(uint4*)(g_Afl + off)     = *(uint4*)(lb);
        *(uint4*)(g_Afl + off + 8) = *(uint4*)(lb + 8);
    }
    {   // (b) Xf rows (fp16 hi + residual) + inv norm
        const int i = c * 256 + tid;
        alignas(16) __half hb[16], lb[16];
        float s2 = 0.f;
#pragma unroll
        for (int t = 0; t < 16; t++) {
            float v = s[t][tid];
            s2 = fmaf(v, v, s2);
            __half h = __float2half(v);
            hb[t] = h;
            lb[t] = __float2half(v - __half2float(h));
        }
        g_inorm[g * 1024 + i] = rsqrtf(s2);
        size_t off = (size_t)(g * 1024 + i) * 16;
        *(uint4*)(g_Xfh + off)     = *(uint4*)(hb);
        *(uint4*)(g_Xfh + off + 8) = *(uint4*)(hb + 8);
        *(uint4*)(g_Xfl + off)     = *(uint4*)(lb);
        *(uint4*)(g_Xfl + off + 8) = *(uint4*)(lb + 8);
    }
    {   // (c) XT rows (fp16 hi + residual)
        const int t = tid >> 4;
        const int ib = (tid & 15) * 16;
        alignas(16) __half hb[16], lb[16];
#pragma unroll
        for (int q = 0; q < 16; q++) {
            float v = s[t][ib + q];
            __half h = __float2half(v);
            hb[q] = h;
            lb[q] = __float2half(v - __half2float(h));
        }
        size_t off = (size_t)(g * 16 + t) * 1024 + c * 256 + ib;
        *(uint4*)(g_XTfh + off)     = *(uint4*)(hb);
        *(uint4*)(g_XTfh + off + 8) = *(uint4*)(hb + 8);
        *(uint4*)(g_XTfl + off)     = *(uint4*)(lb);
        *(uint4*)(g_XTfl + off + 8) = *(uint4*)(lb + 8);
    }
}

// P2: 64x64 tiles -> single fp16 B
__device__ __forceinline__ void p2_body(uint8_t* spre, const float* __restrict__ Lk,
                                        int jt, int kt)
{
    float (*s)[65] = (float(*)[65])spre;   // [64 j][65]
    const int tid = threadIdx.x;
#pragma unroll
    for (int q = 0; q < 16; q++) {
        int idx = tid + q * 256;
        int row = idx >> 6;       // k-local 0..63
        int col = idx & 63;       // j-local
        s[col][row] = Lk[(kt * 64 + row) * 3072 + 1024 + jt * 64 + col];
    }
    __syncthreads();
#pragma unroll
    for (int q = 0; q < 4; q++) {
        int u = tid + q * 256;
        int jy = u >> 4;              // 0..63
        int kg = (u & 15) * 4;        // 0..60
        alignas(8) __half hb[4];
#pragma unroll
        for (int w = 0; w < 4; w++)
            hb[w] = __float2half(s[jy][kg + w]);
        size_t off = (size_t)(jt * 64 + jy) * 1024 + kt * 64 + kg;
        *(uint64_t*)(g_Bf + off) = *(uint64_t*)hb;
    }
}

// P3: beta -> fragment-ordered fp16 (8 halves = 16B per lane-entry)
__device__ __forceinline__ void p3_body(const float* __restrict__ beta, int blk)
{
    const int idx = blk * 256 + threadIdx.x;    // 0..131071
    const int lane = idx & 31;
    const int js = (idx >> 5) & 63;
    const int ib = idx >> 11;
    const int g = lane >> 2, tg = lane & 3;
    const int r0 = ib * 16 + g, r1 = r0 + 8;
    const int c0 = js * 16 + 2 * tg, c1 = c0 + 8;
    const float* b0 = beta + (size_t)r0 * 1024;
    const float* b1 = beta + (size_t)r1 * 1024;
    float2 a0 = *(const float2*)(b0 + c0);
    float2 a1 = *(const float2*)(b0 + c1);
    float2 a2 = *(const float2*)(b1 + c0);
    float2 a3 = *(const float2*)(b1 + c1);
    alignas(16) __half hb[8];
    hb[0] = __float2half(a0.x); hb[1] = __float2half(a0.y);
    hb[2] = __float2half(a1.x); hb[3] = __float2half(a1.y);
    hb[4] = __float2half(a2.x); hb[5] = __float2half(a2.y);
    hb[6] = __float2half(a3.x); hb[7] = __float2half(a3.y);
    *(uint4*)(g_bpermh + (size_t)idx * 8) = *(uint4*)hb;
}

__global__ __launch_bounds__(256) void k_pre(const float* __restrict__ x,
                                             const float* __restrict__ Lk,
                                             const float* __restrict__ beta)
{
    __shared__ __align__(16) uint8_t spre[16640];
    const int bid = blockIdx.x;
    if (bid < 256) p1_body(spre, x, bid >> 2, bid & 3);
    else if (bid < 768) p2_body(spre, Lk, (bid - 256) & 31, (bid - 256) >> 5);
    else p3_body(beta, bid - 768);
}

// =============================================================================
// Heavy fused kernel: even blocks = k1 GEMM tile, odd blocks = k3t attention.
// Resource footprint (smem 36864, stage stride 12288) kept identical to the
// measured-good R14 config; k1 uses only [0,8192) of each stage.
// =============================================================================
// K1 fp16 2-pass: (Ahi + Alo) x B_single.
// stage s at sm + s*12288: Afh[0,2048) Afl[2048,4096) Bf[4096,8192) pad[8192,12288)
__device__ __forceinline__ void k1_body(uint8_t* sm, int bid)
{
    const int tid = threadIdx.x;
    const int wid = tid >> 5, lane = tid & 31;
    const int g = lane >> 2, tg = lane & 3;
    const int wm = (wid & 3) * 16;
    const int wn = (wid >> 2) * 64;
    const int row0 = (bid >> 4) * 64;
    const int col0 = (bid & 15) * 128;

    const __half* Asrc_h = g_Afh + (size_t)row0 * 1024;
    const __half* Asrc_l = g_Afl + (size_t)row0 * 1024;
    const __half* Bsrc   = g_Bf  + (size_t)col0 * 1024;

    float acc[8][4];
#pragma unroll
    for (int nt = 0; nt < 8; nt++)
#pragma unroll
        for (int q = 0; q < 4; q++) acc[nt][q] = 0.f;

    auto load_stage = [&](int s, int kt) {
#pragma unroll
        for (int q = 0; q < 2; q++) {
            int idx = tid + q * 256;          // 0..511
            const __half* src;
            uint32_t arr_off;
            int rc;
            if (idx < 256) {                  // A: 64 rows x 2 chunks, hi|lo
                rc = idx & 127;
                src = (idx < 128) ? Asrc_h : Asrc_l;
                arr_off = (idx < 128) ? 0 : 2048;
            } else {                          // B: 128 rows x 2 chunks
                rc = idx - 256;
                src = Bsrc;
                arr_off = 4096;
            }
            int r = rc >> 1, c = rc & 1;
            uint32_t dst = smem_u32(sm) + s * 12288 + arr_off + r * 32 +
                           ((c * 16) ^ (((r >> 2) & 1) << 4));
            cp_async16(dst, src + (size_t)r * 1024 + kt * 16 + c * 8);
        }
        cp_commit();
    };

    uint32_t offA, offB[4];
    {
        int arow = ((lane >> 3) & 1) * 8 + (lane & 7);
        int cA = lane >> 4;
        int brow = ((lane >> 4) << 3) + (lane & 7);
        int cB = (lane >> 3) & 1;
        int rA = wm + arow;
        offA = rA * 32 + ((cA ^ ((rA >> 2) & 1)) << 4);
#pragma unroll
        for (int p = 0; p < 4; p++) {
            int r = wn + p * 16 + brow;
            offB[p] = r * 32 + ((cB ^ ((r >> 2) & 1)) << 4);
        }
    }

    load_stage(0, 0);
    load_stage(1, 1);

    int sread = 0;
    for (int kt = 0; kt < 64; kt++) {
        if (kt < 63) cp_wait<1>(); else cp_wait<0>();
        __syncthreads();
        if (kt + 2 < 64) {
            int sw = sread + 2; if (sw >= 3) sw -= 3;
            load_stage(sw, kt + 2);
        }

        const uint32_t base = smem_u32(sm) + sread * 12288;

        uint32_t ah[4], al[4], bf[4][4];
        ldsm_x4(ah, base + offA);
        ldsm_x4(al, base + 2048 + offA);
#pragma unroll
        for (int p = 0; p < 4; p++)
            ldsm_x4(bf[p], base + 4096 + offB[p]);

#pragma unroll
        for (int nt = 0; nt < 8; nt++)
            mma16816f16(acc[nt], ah, &bf[nt >> 1][(nt & 1) * 2]);
#pragma unroll
        for (int nt = 0; nt < 8; nt++)
            mma16816f16(acc[nt], al, &bf[nt >> 1][(nt & 1) * 2]);

        sread = (sread + 1 == 3) ? 0 : sread + 1;
    }
#pragma unroll
    for (int nt = 0; nt < 8; nt++) {
        int r = row0 + wm + g;
        int c = col0 + wn + nt * 8 + tg * 2;
        *(float2*)&g_XM[(size_t)r * 2048 + c] =
            make_float2(acc[nt][0], acc[nt][1]);
        *(float2*)&g_XM[(size_t)(r + 8) * 2048 + c] =
            make_float2(acc[nt][2], acc[nt][3]);
    }
}

// K3T: identical to R14 config. S = 2-pass fp16 (Xi hi/lo x Xj-hi),
// PV = 3-pass fp16 (Phi x XTh + Phi x XTl + Plo x XTh).
// stage st at sm + st*12288: Xj[0,4096) XTh[4096,8192) XTl[8192,12288)
// sInj at sm + 24576.
__device__ __forceinline__ void k3t_body(uint8_t* sm, int bid)
{
    float* sInj = (float*)(sm + 24576);

    const int tid  = threadIdx.x;
    const int lane = tid & 31, wid = tid >> 5;
    const int g = lane >> 2, tg = lane & 3;
    const int bc = bid >> 2;
    const int i0 = (bid & 3) * 256;

    for (int q = tid; q < 1024; q += 256) sInj[q] = g_inorm[bc * 1024 + q];

    const int rw = i0 + wid * 32;
    const int ib0 = rw >> 4;

    uint32_t aih[2][4], ail[2][4];
    float nia[2], nib[2];
#pragma unroll
    for (int p = 0; p < 2; p++) {
        const int r = rw + 16 * p + g;
        const uint32_t* Xh = (const uint32_t*)(g_Xfh + ((size_t)bc * 1024 + r) * 16);
        const uint32_t* Xl = (const uint32_t*)(g_Xfl + ((size_t)bc * 1024 + r) * 16);
        aih[p][0] = Xh[tg];      aih[p][1] = Xh[64 + tg];
        aih[p][2] = Xh[tg + 4];  aih[p][3] = Xh[64 + tg + 4];
        ail[p][0] = Xl[tg];      ail[p][1] = Xl[64 + tg];
        ail[p][2] = Xl[tg + 4];  ail[p][3] = Xl[64 + tg + 4];
        nia[p] = g_inorm[bc * 1024 + r];
        nib[p] = g_inorm[bc * 1024 + r + 8];
    }

    float o[2][2][4];
#pragma unroll
    for (int p = 0; p < 2; p++)
#pragma unroll
        for (int u = 0; u < 2; u++)
#pragma unroll
            for (int q = 0; q < 4; q++) o[p][u][q] = 0.f;

    const int jr = ((lane >> 4) << 3) + (lane & 7);
    const int cS = (lane >> 3) & 1;
    const uint32_t offS = (uint32_t)(jr * 32 + ((cS ^ ((jr >> 2) & 1)) << 4));
    const int tl = jr;
    const int cbit = (lane >> 3) & 1;

    auto stage = [&](int st, int jt) {
        const size_t xb = ((size_t)bc * 1024 + jt * 128) * 32;   // bytes (fp16 row 32B)
        const size_t tb = ((size_t)bc * 16384 + jt * 128) * 2;   // bytes
        const char* srcs[3] = {(const char*)g_Xfh + xb,
                               (const char*)g_XTfh + tb, (const char*)g_XTfl + tb};
#pragma unroll
        for (int a = 0; a < 3; a++) {
            int q = tid;
            uint32_t dst;
            const char* src;
            if (a == 0) {
                int j = q >> 1, c = q & 1;
                dst = (uint32_t)(j * 32 + ((c ^ ((j >> 2) & 1)) << 4));
                src = srcs[0] + (size_t)j * 32 + c * 16;
            } else {
                int t = q >> 4, c = q & 15;
                dst = (uint32_t)(t * 256 + ((c ^ t) << 4));
                src = srcs[a] + (size_t)t * 2048 + c * 16;
            }
            cp_async16(smem_u32(sm) + st * 12288 + a * 4096 + dst, src);
        }
        cp_commit();
    };

    __syncthreads();            // sInj ready
    stage(0, 0);

    for (int jt = 0; jt < 8; jt++) {
        cp_wait<0>();
        __syncthreads();
        if (jt < 7) stage((jt + 1) & 1, jt + 1);

        const uint32_t sbase = smem_u32(sm) + (jt & 1) * 12288;

#pragma unroll 2
        for (int s2 = 0; s2 < 8; s2++) {
            const int js = s2 * 16;
            const int jabs = jt * 128 + js;
            const int jstep = jt * 8 + s2;

            // hoisted beta fragment loads (1 LDG.128 per pair)
            const uint4* bp0 = (const uint4*)g_bpermh +
                               (((size_t)ib0 * 64 + jstep) * 32 + lane);
            uint4 raw0 = bp0[0];
            uint4 raw1 = bp0[64 * 32];     // ib0+1

            uint32_t bh4[4];
            ldsm_x4(bh4, sbase + js * 32 + offS);
            const uint32_t cj = 2 * s2 + cbit;
            const uint32_t offP = (uint32_t)(tl * 256 + ((cj ^ tl) << 4));
            uint32_t th4[4], tl4[4];
            ldsm_x4(th4, sbase + 4096 + offP);
            ldsm_x4(tl4, sbase + 8192 + offP);

            float2 nj0 = *(const float2*)&sInj[jabs + 2 * tg];
            float2 nj1 = *(const float2*)&sInj[jabs + 8 + 2 * tg];

#pragma unroll
            for (int p = 0; p < 2; p++) {
                uint4 raw = (p == 0) ? raw0 : raw1;
                float2 w0 = h2f(raw.x);   // row g:   j0, j0+1
                float2 w1 = h2f(raw.y);   // row g:   j8, j8+1
                float2 w2 = h2f(raw.z);   // row 8+g: j0, j0+1
                float2 w3 = h2f(raw.w);   // row 8+g: j8, j8+1

                float s0[4] = {0.f, 0.f, 0.f, 0.f};
                float s1[4] = {0.f, 0.f, 0.f, 0.f};
                mma16816f16(s0, aih[p], &bh4[0]);
                mma16816f16(s0, ail[p], &bh4[0]);
                mma16816f16(s1, aih[p], &bh4[2]);
                mma16816f16(s1, ail[p], &bh4[2]);

                float p00 = sig_tanh(w0.x * s0[0] * nia[p] * nj0.x);
                float p01 = sig_tanh(w0.y * s0[1] * nia[p] * nj0.y);
                float p02 = sig_tanh(w2.x * s0[2] * nib[p] * nj0.x);
                float p03 = sig_tanh(w2.y * s0[3] * nib[p] * nj0.y);
                float p10 = sig_tanh(w1.x * s1[0] * nia[p] * nj1.x);
                float p11 = sig_tanh(w1.y * s1[1] * nia[p] * nj1.y);
                float p12 = sig_tanh(w3.x * s1[2] * nib[p] * nj1.x);
                float p13 = sig_tanh(w3.y * s1[3] * nib[p] * nj1.y);

                // P split: hi fp16 + residual fp16
                uint32_t pah[4], pal[4];
                pah[0] = pack_f16x2(p01, p00);
                pah[1] = pack_f16x2(p03, p02);
                pah[2] = pack_f16x2(p11, p10);
                pah[3] = pack_f16x2(p13, p12);
                {
                    float2 b0 = h2f(pah[0]), b1 = h2f(pah[1]);
                    float2 b2 = h2f(pah[2]), b3 = h2f(pah[3]);
                    pal[0] = pack_f16x2(p01 - b0.y, p00 - b0.x);
                    pal[1] = pack_f16x2(p03 - b1.y, p02 - b1.x);
                    pal[2] = pack_f16x2(p11 - b2.y, p10 - b2.x);
                    pal[3] = pack_f16x2(p13 - b3.y, p12 - b3.x);
                }

                mma16816f16(o[p][0], pah, &th4[0]);
                mma16816f16(o[p][0], pah, &tl4[0]);
                mma16816f16(o[p][0], pal, &th4[0]);
                mma16816f16(o[p][1], pah, &th4[2]);
                mma16816f16(o[p][1], pah, &tl4[2]);
                mma16816f16(o[p][1], pal, &th4[2]);
            }
        }
    }

    // epilogue: dense float2 stores into g_cos[bc][i][t]
#pragma unroll
    for (int p = 0; p < 2; p++) {
        const int r = rw + 16 * p + g;
        float* base0 = g_cos + ((size_t)bc * 1024 + r) * 16;      // row r
        float* base1 = base0 + 8 * 16;                            // row r+8
        *(float2*)(base0 + 2 * tg)     = make_float2(o[p][0][0], o[p][0][1]);
        *(float2*)(base1 + 2 * tg)     = make_float2(o[p][0][2], o[p][0][3]);
        *(float2*)(base0 + 8 + 2 * tg) = make_float2(o[p][1][0], o[p][1][1]);
        *(float2*)(base1 + 8 + 2 * tg) = make_float2(o[p][1][2], o[p][1][3]);
    }
}

__global__ __launch_bounds__(256, 2) void k_heavy()
{
    __shared__ __align__(16) uint8_t sm[36864];
    if ((blockIdx.x & 1) == 0) k1_body(sm, blockIdx.x >> 1);
    else                       k3t_body(sm, blockIdx.x >> 1);
}

// =============================================================================
// K_POST: fused theta-fold + relu/mul + channel softmax.
// =============================================================================
__global__ __launch_bounds__(256) void k_post(const float* __restrict__ x,
                                              const float* __restrict__ theta,
                                              const float* __restrict__ bias,
                                              float* __restrict__ out)
{
    __shared__ float th[768];
    __shared__ float bs[16];
    __shared__ float sx[16][16][17];     // [c][il][t]
    __shared__ float scos[16][272];      // [ch][t*17 + il]

    const int tid = threadIdx.x;
    const int tau = tid >> 4, il = tid & 15;
    const int b  = blockIdx.x >> 6;
    const int i0 = (blockIdx.x & 63) * 16;
    const int i  = i0 + il;

    for (int q = tid; q < 768; q += 256) th[q] = theta[q];
    if (tid < 16) bs[tid] = bias[tid];

    // stage cos: per ch, 256 consecutive floats (16 i x 16 t), coalesced
    {
        const int il2 = tid >> 4, tau2 = tid & 15;
#pragma unroll
        for (int ch = 0; ch < 16; ch++)
            scos[ch][tau2 * 17 + il2] =
                g_cos[((size_t)(b * 16 + ch) << 14) + i0 * 16 + tid];
    }

    const float* xr = x + (((b << 4) + tau) << 14) + (i << 4);
    float xrow[16];
#pragma unroll
    for (int q = 0; q < 4; q++)
        *(float4*)(xrow + 4 * q) = *(const float4*)(xr + 4 * q);
#pragma unroll
    for (int q = 0; q < 16; q++) sx[tau][il][q] = xrow[q];
    __syncthreads();

    float acc[16];
#pragma unroll
    for (int c = 0; c < 16; c++) acc[c] = bs[c];

    const int rbase = (b << 8) + (tau << 4);
#pragma unroll 4
    for (int tp = 0; tp < 16; ++tp) {
        const float* xm = g_XM + (size_t)(rbase + tp) * 2048 + i;
        float a0 = xrow[tp];
        float a1 = xm[0];
        float a2 = xm[1024];
        const float* t0 = th + tp * 48;
#pragma unroll
        for (int c = 0; c < 16; c++)
            acc[c] += a0 * t0[c] + a1 * t0[16 + c] + a2 * t0[32 + c];
    }

    float gg[16];
#pragma unroll
    for (int c = 0; c < 16; c++) {
        float xv = sx[c][il][tau];          // x[b][c][i][tau]
        float r = acc[c] + xv;
        r = r > 0.f ? r : 0.f;
        gg[c] = scos[c][tau * 17 + il] * r; // cos[b,c][i][tau]
    }
    float m = gg[0];
#pragma unroll
    for (int c = 1; c < 16; c++) m = fmaxf(m, gg[c]);
    float s = 0.f;
#pragma unroll
    for (int c = 0; c < 16; c++) {
        float e = __expf(gg[c] - m);
        gg[c] = e;
        s += e;
    }
    float rs = __fdividef(1.f, s);

#pragma unroll
    for (int c = 0; c < 16; c++) sx[c][il][tau] = gg[c] * rs;
    __syncthreads();

    float* dst = out + (((b << 4) + tau) << 14) + (i << 4);
#pragma unroll
    for (int t = 0; t < 16; t++) dst[t] = sx[tau][il][t];
}

// =============================================================================
extern "C" void kernel_launch(void* const* d_in, const int* in_sizes, int n_in,
                              void* d_out, int out_size)
{
    const float* x     = (const float*)d_in[0];
    const float* beta  = (const float*)d_in[1];
    const float* theta = (const float*)d_in[2];
    const float* bias  = (const float*)d_in[3];
    const float* Lk    = (const float*)d_in[4];
    float* out = (float*)d_out;

    k_pre<<<1280, 256>>>(x, Lk, beta);
    k_heavy<<<512, 256>>>();
    k_post<<<256, 256>>>(x, theta, bias, out);
}